// round 5
// baseline (speedup 1.0000x reference)
#include <cuda_runtime.h>
#include <math.h>

#define NN 100000
#define EE 1600000
#define KK 10
#define HID 64
#define FIN 256

// ---------------- scratch (no allocations allowed) ----------------
__device__ __align__(16) float g_T0[NN * HID];   // scaled states rotate
__device__ __align__(16) float g_T1[NN * HID];
__device__ __align__(16) float g_T2[NN * HID];
__device__ __align__(16) float g_H [NN * HID];   // unscaled h for final pass
__device__ int   g_cnt_row[NN];
__device__ int   g_cnt_col[NN];
__device__ int   g_rowptr[NN + 1];
__device__ int   g_cur[NN];
__device__ float g_dis[NN];    // rsqrt(deg) or 0
__device__ float g_dis2[NN];   // 1/deg or 0
__device__ int   g_rows32[EE];
__device__ int   g_cols32[EE];
__device__ int   g_esrc[EE];
__device__ float g_coe[16];    // [0..10] coefficients, [12] deg-0 fixup
__device__ int   g_tmpinc[NN];
__device__ int   g_bsum[128];
__device__ int   g_boff[128];
__device__ int   g_is64;

// ---------------- dtype detect: int64 edge_index has zero high words ----------------
__global__ void detect_kernel(const unsigned int* __restrict__ ei32) {
    if (threadIdx.x != 0 || blockIdx.x != 0) return;
    int zeros = 0;
    for (int i = 0; i < 8; i++)
        if (ei32[2 * i + 1] == 0u) zeros++;
    g_is64 = (zeros == 8) ? 1 : 0;
}

// ---------------- histogram + convert indices to int32 ----------------
__global__ void hist_kernel(const void* __restrict__ eiv) {
    int e = blockIdx.x * blockDim.x + threadIdx.x;
    if (e >= EE) return;
    int r, c;
    if (g_is64) {
        const long long* ei = (const long long*)eiv;
        r = (int)ei[e];
        c = (int)ei[EE + e];
    } else {
        const int* ei = (const int*)eiv;
        r = ei[e];
        c = ei[EE + e];
    }
    if ((unsigned)r >= NN || (unsigned)c >= NN) { r = 0; c = 0; }
    g_rows32[e] = r;
    g_cols32[e] = c;
    atomicAdd(&g_cnt_row[r], 1);
    atomicAdd(&g_cnt_col[c], 1);
}

// ---------------- dis = rsqrt(deg), dis2 = 1/deg ----------------
__global__ void dis_kernel() {
    int i = blockIdx.x * blockDim.x + threadIdx.x;
    if (i >= NN) return;
    int d = g_cnt_row[i];
    g_dis[i]  = (d > 0) ? rsqrtf((float)d) : 0.0f;
    g_dis2[i] = (d > 0) ? (1.0f / (float)d) : 0.0f;
}

// ---------------- 3-phase exclusive scan of cnt_col -> rowptr ----------------
__global__ void scan1_kernel() {
    __shared__ int s[1024];
    int tid = threadIdx.x;
    int i = blockIdx.x * 1024 + tid;
    int v = (i < NN) ? g_cnt_col[i] : 0;
    s[tid] = v;
    __syncthreads();
    for (int off = 1; off < 1024; off <<= 1) {
        int t = 0;
        if (tid >= off) t = s[tid - off];
        __syncthreads();
        s[tid] += t;
        __syncthreads();
    }
    if (i < NN) g_tmpinc[i] = s[tid];
    if (tid == 1023) g_bsum[blockIdx.x] = s[1023];
}

__global__ void scan2_kernel(int nb) {
    if (blockIdx.x == 0 && threadIdx.x == 0) {
        int run = 0;
        for (int b = 0; b < nb; b++) {
            g_boff[b] = run;
            run += g_bsum[b];
        }
    }
}

__global__ void scan3_kernel() {
    int i = blockIdx.x * blockDim.x + threadIdx.x;
    if (i == 0) g_rowptr[0] = 0;
    if (i < NN) g_rowptr[i + 1] = g_tmpinc[i] + g_boff[i >> 10];
}

// ---------------- scatter edges into CSR-by-dst (src index only) ----------------
__global__ void scatter_kernel() {
    int e = blockIdx.x * blockDim.x + threadIdx.x;
    if (e >= EE) return;
    int r = g_rows32[e];
    int c = g_cols32[e];
    int p = atomicAdd(&g_cur[c], 1);
    g_esrc[p] = r;
}

// ---------------- Chebyshev coefficients from temp ----------------
__global__ void coe_kernel(const float* __restrict__ temp) {
    if (blockIdx.x != 0 || threadIdx.x != 0) return;
    double xs[KK + 1];
    float m0[KK + 1], m1[KK + 1], tv[KK + 1];
    for (int j = 0; j <= KK; j++) {
        xs[j] = cos((KK - j + 0.5) * M_PI / (KK + 1));
        tv[j] = temp[j];
    }
    const float f = 2.0f / (KK + 1);
    float s0 = 0.f, s1 = 0.f;
    for (int j = 0; j <= KK; j++) {
        m0[j] = 1.0f;
        m1[j] = (float)xs[j];
        s0 += tv[j] * m0[j];
        s1 += tv[j] * m1[j];
    }
    g_coe[0] = f * s0;
    g_coe[1] = f * s1;
    for (int i = 2; i <= KK; i++) {
        float s = 0.f;
        for (int j = 0; j <= KK; j++) {
            float m2 = (float)(2.0 * xs[j] * (double)m1[j] - (double)m0[j]);
            s += tv[j] * m2;
            m0[j] = m1[j];
            m1[j] = m2;
        }
        g_coe[i] = f * s;
    }
    // deg-0 node fixup: T_{2m} = (-1)^m h, T_odd = 0
    g_coe[12] = 0.5f * g_coe[0] - g_coe[2] + g_coe[4] - g_coe[6] + g_coe[8] - g_coe[10];
}

// ---------------- fused MLP: h = relu(x@W1+b1)@W2+b2 ; writes h and dis*h ----------------
__global__ __launch_bounds__(256) void mlp_kernel(
    const float* __restrict__ x, const float* __restrict__ W1,
    const float* __restrict__ b1, const float* __restrict__ W2,
    const float* __restrict__ b2, float* __restrict__ h,
    float* __restrict__ hs)
{
    __shared__ __align__(16) float sbuf[64 * 33 + 32 * 64];
    __shared__ __align__(16) float Hs[64 * 65];
    float* Xs = sbuf;
    float* Ws = sbuf + 64 * 33;

    int tid = threadIdx.x;
    int tx = tid & 15;
    int ty = tid >> 4;
    int row0 = blockIdx.x * 64;

    float acc[4][4];
#pragma unroll
    for (int i = 0; i < 4; i++)
#pragma unroll
        for (int j = 0; j < 4; j++) acc[i][j] = 0.f;

    for (int kc = 0; kc < FIN; kc += 32) {
        for (int i = tid; i < 64 * 32; i += 256) {
            int r = i >> 5, k = i & 31;
            int gr = row0 + r;
            Xs[r * 33 + k] = (gr < NN) ? x[gr * FIN + kc + k] : 0.f;
        }
        for (int i = tid; i < 32 * 64; i += 256) {
            int k = i >> 6, j = i & 63;
            Ws[i] = W1[(kc + k) * HID + j];
        }
        __syncthreads();
#pragma unroll
        for (int k = 0; k < 32; k++) {
            float a0 = Xs[(ty * 4 + 0) * 33 + k];
            float a1 = Xs[(ty * 4 + 1) * 33 + k];
            float a2 = Xs[(ty * 4 + 2) * 33 + k];
            float a3 = Xs[(ty * 4 + 3) * 33 + k];
            float4 b = *(const float4*)&Ws[k * 64 + tx * 4];
            acc[0][0] += a0 * b.x; acc[0][1] += a0 * b.y; acc[0][2] += a0 * b.z; acc[0][3] += a0 * b.w;
            acc[1][0] += a1 * b.x; acc[1][1] += a1 * b.y; acc[1][2] += a1 * b.z; acc[1][3] += a1 * b.w;
            acc[2][0] += a2 * b.x; acc[2][1] += a2 * b.y; acc[2][2] += a2 * b.z; acc[2][3] += a2 * b.w;
            acc[3][0] += a3 * b.x; acc[3][1] += a3 * b.y; acc[3][2] += a3 * b.z; acc[3][3] += a3 * b.w;
        }
        __syncthreads();
    }

    float4 bb = *(const float4*)&b1[tx * 4];
#pragma unroll
    for (int i = 0; i < 4; i++) {
        int r = ty * 4 + i;
        Hs[r * 65 + tx * 4 + 0] = fmaxf(acc[i][0] + bb.x, 0.f);
        Hs[r * 65 + tx * 4 + 1] = fmaxf(acc[i][1] + bb.y, 0.f);
        Hs[r * 65 + tx * 4 + 2] = fmaxf(acc[i][2] + bb.z, 0.f);
        Hs[r * 65 + tx * 4 + 3] = fmaxf(acc[i][3] + bb.w, 0.f);
    }
    for (int i = tid; i < 64 * 64; i += 256) sbuf[i] = W2[i];
    __syncthreads();

    float acc2[4][4];
#pragma unroll
    for (int i = 0; i < 4; i++)
#pragma unroll
        for (int j = 0; j < 4; j++) acc2[i][j] = 0.f;

#pragma unroll
    for (int k = 0; k < 64; k++) {
        float a0 = Hs[(ty * 4 + 0) * 65 + k];
        float a1 = Hs[(ty * 4 + 1) * 65 + k];
        float a2 = Hs[(ty * 4 + 2) * 65 + k];
        float a3 = Hs[(ty * 4 + 3) * 65 + k];
        float4 b = *(const float4*)&sbuf[k * 64 + tx * 4];
        acc2[0][0] += a0 * b.x; acc2[0][1] += a0 * b.y; acc2[0][2] += a0 * b.z; acc2[0][3] += a0 * b.w;
        acc2[1][0] += a1 * b.x; acc2[1][1] += a1 * b.y; acc2[1][2] += a1 * b.z; acc2[1][3] += a1 * b.w;
        acc2[2][0] += a2 * b.x; acc2[2][1] += a2 * b.y; acc2[2][2] += a2 * b.z; acc2[2][3] += a2 * b.w;
        acc2[3][0] += a3 * b.x; acc2[3][1] += a3 * b.y; acc2[3][2] += a3 * b.z; acc2[3][3] += a3 * b.w;
    }

    float4 c2 = *(const float4*)&b2[tx * 4];
#pragma unroll
    for (int i = 0; i < 4; i++) {
        int gr = row0 + ty * 4 + i;
        if (gr < NN) {
            float4 o;
            o.x = acc2[i][0] + c2.x;
            o.y = acc2[i][1] + c2.y;
            o.z = acc2[i][2] + c2.z;
            o.w = acc2[i][3] + c2.w;
            *(float4*)&h[gr * HID + tx * 4] = o;
            float dv = g_dis[gr];
            float4 os;
            os.x = dv * o.x; os.y = dv * o.y; os.z = dv * o.z; os.w = dv * o.w;
            *(float4*)&hs[gr * HID + tx * 4] = os;
        }
    }
}

// ---------------- fused Chebyshev propagation (scaled space) ----------------
// Warp per node; two 16-lane halves split edge chunks (even/odd), each lane owns
// 4 features (float4). Gather = pure sum of scaled rows (no weights!).
//   first=1: T̃1 = -dis2*g;            out  = coe[1]*T̃1
//   first=0: T̃i = -2*dis2*g - T̃_{i-2}; out += coe[ci]*T̃i
__global__ __launch_bounds__(256) void prop_kernel(
    const float4* __restrict__ v, const float4* __restrict__ prev,
    float4* __restrict__ dst, float4* __restrict__ outv,
    int ci, int first)
{
    int tid = threadIdx.x;
    int node = blockIdx.x * 8 + (tid >> 5);
    if (node >= NN) return;
    int half = (tid >> 4) & 1;
    int lane = tid & 15;
    unsigned hmask = 0xFFFFu << ((tid & 16));

    int beg = g_rowptr[node];
    int end = g_rowptr[node + 1];

    float4 acc = make_float4(0.f, 0.f, 0.f, 0.f);
    for (int p = beg + half * 16; p < end; p += 32) {
        int cnt = min(16, end - p);
        int s = (lane < cnt) ? __ldg(&g_esrc[p + lane]) : 0;
        for (int j = 0; j < cnt; j++) {
            int sj = __shfl_sync(hmask, s, j, 16);
            float4 val = __ldg(&v[sj * 16 + lane]);
            acc.x += val.x; acc.y += val.y; acc.z += val.z; acc.w += val.w;
        }
    }
    // combine the two halves
    acc.x += __shfl_xor_sync(0xffffffffu, acc.x, 16);
    acc.y += __shfl_xor_sync(0xffffffffu, acc.y, 16);
    acc.z += __shfl_xor_sync(0xffffffffu, acc.z, 16);
    acc.w += __shfl_xor_sync(0xffffffffu, acc.w, 16);

    int idx = node * 16 + lane;
    float d2 = g_dis2[node];
    float c = g_coe[ci];
    float4 t;
    if (first) {
        t.x = -d2 * acc.x;
        t.y = -d2 * acc.y;
        t.z = -d2 * acc.z;
        t.w = -d2 * acc.w;
    } else {
        float4 pv = __ldg(&prev[idx]);
        float m = -2.f * d2;
        t.x = fmaf(m, acc.x, -pv.x);
        t.y = fmaf(m, acc.y, -pv.y);
        t.z = fmaf(m, acc.z, -pv.z);
        t.w = fmaf(m, acc.w, -pv.w);
    }
    if (half == 0) {
        dst[idx] = t;
    } else {
        float4 o;
        if (first) {
            o.x = c * t.x; o.y = c * t.y; o.z = c * t.z; o.w = c * t.w;
        } else {
            o = outv[idx];
            o.x += c * t.x; o.y += c * t.y; o.z += c * t.z; o.w += c * t.w;
        }
        outv[idx] = o;
    }
}

// ---------------- final: out = coe0/2*h + õ/dis  (deg-0: fixup*h) ----------------
__global__ __launch_bounds__(256) void final_kernel(
    float4* __restrict__ outv, const float4* __restrict__ h)
{
    int i = blockIdx.x * 256 + threadIdx.x;
    if (i >= NN * 16) return;
    int node = i >> 4;
    float dis = g_dis[node];
    float4 hv = __ldg(&h[i]);
    float4 o = outv[i];
    if (dis > 0.f) {
        float c0h = 0.5f * g_coe[0];
        float inv = 1.0f / dis;
        o.x = c0h * hv.x + o.x * inv;
        o.y = c0h * hv.y + o.y * inv;
        o.z = c0h * hv.z + o.z * inv;
        o.w = c0h * hv.w + o.w * inv;
    } else {
        float fx = g_coe[12];
        o.x = fx * hv.x; o.y = fx * hv.y; o.z = fx * hv.z; o.w = fx * hv.w;
    }
    outv[i] = o;
}

// ---------------- launch ----------------
extern "C" void kernel_launch(void* const* d_in, const int* in_sizes, int n_in,
                              void* d_out, int out_size) {
    const float* x    = (const float*)d_in[0];
    const void*  ei   = d_in[1];
    const float* W1   = (const float*)d_in[2];
    const float* b1   = (const float*)d_in[3];
    const float* W2   = (const float*)d_in[4];
    const float* b2   = (const float*)d_in[5];
    const float* temp = (const float*)d_in[6];
    float4*      out4 = (float4*)d_out;

    void *pT0, *pT1, *pT2, *pH, *pCntR, *pCntC, *pRowptr, *pCur;
    cudaGetSymbolAddress(&pT0, g_T0);
    cudaGetSymbolAddress(&pT1, g_T1);
    cudaGetSymbolAddress(&pT2, g_T2);
    cudaGetSymbolAddress(&pH,  g_H);
    cudaGetSymbolAddress(&pCntR, g_cnt_row);
    cudaGetSymbolAddress(&pCntC, g_cnt_col);
    cudaGetSymbolAddress(&pRowptr, g_rowptr);
    cudaGetSymbolAddress(&pCur, g_cur);

    // --- graph preprocessing ---
    cudaMemsetAsync(pCntR, 0, NN * sizeof(int), 0);
    cudaMemsetAsync(pCntC, 0, NN * sizeof(int), 0);
    detect_kernel<<<1, 32>>>((const unsigned int*)ei);
    hist_kernel<<<(EE + 255) / 256, 256>>>(ei);
    dis_kernel<<<(NN + 255) / 256, 256>>>();
    int nb = (NN + 1023) / 1024;
    scan1_kernel<<<nb, 1024>>>();
    scan2_kernel<<<1, 1>>>(nb);
    scan3_kernel<<<(NN + 255) / 256, 256>>>();
    cudaMemcpyAsync(pCur, pRowptr, NN * sizeof(int), cudaMemcpyDeviceToDevice, 0);
    scatter_kernel<<<(EE + 255) / 256, 256>>>();

    // --- coefficients ---
    coe_kernel<<<1, 32>>>(temp);

    // --- MLP -> g_H (h) and g_T0 (dis*h = T̃0) ---
    mlp_kernel<<<(NN + 63) / 64, 256>>>(x, W1, b1, W2, b2, (float*)pH, (float*)pT0);

    // --- Chebyshev recurrence in scaled space ---
    int pgrid = (NN + 7) / 8;
    prop_kernel<<<pgrid, 256>>>((const float4*)pT0, (const float4*)pT0,
                                (float4*)pT1, out4, 1, 1);
    float4* t0 = (float4*)pT0;
    float4* t1 = (float4*)pT1;
    float4* t2 = (float4*)pT2;
    for (int i = 2; i <= KK; i++) {
        prop_kernel<<<pgrid, 256>>>(t1, t0, t2, out4, i, 0);
        float4* tmp = t0; t0 = t1; t1 = t2; t2 = tmp;
    }

    // --- final unscale + h term ---
    final_kernel<<<(NN * 16 + 255) / 256, 256>>>(out4, (const float4*)pH);
}

// round 7
// speedup vs baseline: 1.0003x; 1.0003x over previous
#include <cuda_runtime.h>
#include <math.h>

#define NN 100000
#define EE 1600000
#define KK 10
#define HID 64
#define FIN 256

// ---------------- scratch (no allocations allowed) ----------------
__device__ __align__(16) float g_T0[NN * HID];   // scaled states rotate
__device__ __align__(16) float g_T1[NN * HID];
__device__ __align__(16) float g_T2[NN * HID];
__device__ __align__(16) float g_H [NN * HID];   // unscaled h for final pass
__device__ int   g_cnt_row[NN];
__device__ int   g_cnt_col[NN];
__device__ int   g_rowptr[NN + 1];
__device__ int   g_cur[NN];
__device__ float g_dis[NN];    // rsqrt(deg) or 0
__device__ float g_dis2[NN];   // 1/deg or 0
__device__ int   g_rows32[EE];
__device__ int   g_cols32[EE];
__device__ int   g_esrc[EE];
__device__ float g_coe[16];    // [0..10] coefficients, [12] deg-0 fixup
__device__ int   g_tmpinc[NN];
__device__ int   g_bsum[128];
__device__ int   g_boff[128];
__device__ int   g_is64;

// ---------------- dtype detect: int64 edge_index has zero high words ----------------
__global__ void detect_kernel(const unsigned int* __restrict__ ei32) {
    if (threadIdx.x != 0 || blockIdx.x != 0) return;
    int zeros = 0;
    for (int i = 0; i < 8; i++)
        if (ei32[2 * i + 1] == 0u) zeros++;
    g_is64 = (zeros == 8) ? 1 : 0;
}

// ---------------- histogram + convert indices to int32 ----------------
__global__ void hist_kernel(const void* __restrict__ eiv) {
    int e = blockIdx.x * blockDim.x + threadIdx.x;
    if (e >= EE) return;
    int r, c;
    if (g_is64) {
        const long long* ei = (const long long*)eiv;
        r = (int)ei[e];
        c = (int)ei[EE + e];
    } else {
        const int* ei = (const int*)eiv;
        r = ei[e];
        c = ei[EE + e];
    }
    if ((unsigned)r >= NN || (unsigned)c >= NN) { r = 0; c = 0; }
    g_rows32[e] = r;
    g_cols32[e] = c;
    atomicAdd(&g_cnt_row[r], 1);
    atomicAdd(&g_cnt_col[c], 1);
}

// ---------------- dis = rsqrt(deg), dis2 = 1/deg ----------------
__global__ void dis_kernel() {
    int i = blockIdx.x * blockDim.x + threadIdx.x;
    if (i >= NN) return;
    int d = g_cnt_row[i];
    g_dis[i]  = (d > 0) ? rsqrtf((float)d) : 0.0f;
    g_dis2[i] = (d > 0) ? (1.0f / (float)d) : 0.0f;
}

// ---------------- 3-phase exclusive scan of cnt_col -> rowptr ----------------
__global__ void scan1_kernel() {
    __shared__ int s[1024];
    int tid = threadIdx.x;
    int i = blockIdx.x * 1024 + tid;
    int v = (i < NN) ? g_cnt_col[i] : 0;
    s[tid] = v;
    __syncthreads();
    for (int off = 1; off < 1024; off <<= 1) {
        int t = 0;
        if (tid >= off) t = s[tid - off];
        __syncthreads();
        s[tid] += t;
        __syncthreads();
    }
    if (i < NN) g_tmpinc[i] = s[tid];
    if (tid == 1023) g_bsum[blockIdx.x] = s[1023];
}

__global__ void scan2_kernel(int nb) {
    if (blockIdx.x == 0 && threadIdx.x == 0) {
        int run = 0;
        for (int b = 0; b < nb; b++) {
            g_boff[b] = run;
            run += g_bsum[b];
        }
    }
}

__global__ void scan3_kernel() {
    int i = blockIdx.x * blockDim.x + threadIdx.x;
    if (i == 0) g_rowptr[0] = 0;
    if (i < NN) g_rowptr[i + 1] = g_tmpinc[i] + g_boff[i >> 10];
}

// ---------------- scatter edges into CSR-by-dst (src index only) ----------------
__global__ void scatter_kernel() {
    int e = blockIdx.x * blockDim.x + threadIdx.x;
    if (e >= EE) return;
    int r = g_rows32[e];
    int c = g_cols32[e];
    int p = atomicAdd(&g_cur[c], 1);
    g_esrc[p] = r;
}

// ---------------- Chebyshev coefficients from temp ----------------
__global__ void coe_kernel(const float* __restrict__ temp) {
    if (blockIdx.x != 0 || threadIdx.x != 0) return;
    double xs[KK + 1];
    float m0[KK + 1], m1[KK + 1], tv[KK + 1];
    for (int j = 0; j <= KK; j++) {
        xs[j] = cos((KK - j + 0.5) * M_PI / (KK + 1));
        tv[j] = temp[j];
    }
    const float f = 2.0f / (KK + 1);
    float s0 = 0.f, s1 = 0.f;
    for (int j = 0; j <= KK; j++) {
        m0[j] = 1.0f;
        m1[j] = (float)xs[j];
        s0 += tv[j] * m0[j];
        s1 += tv[j] * m1[j];
    }
    g_coe[0] = f * s0;
    g_coe[1] = f * s1;
    for (int i = 2; i <= KK; i++) {
        float s = 0.f;
        for (int j = 0; j <= KK; j++) {
            float m2 = (float)(2.0 * xs[j] * (double)m1[j] - (double)m0[j]);
            s += tv[j] * m2;
            m0[j] = m1[j];
            m1[j] = m2;
        }
        g_coe[i] = f * s;
    }
    // deg-0 node fixup: T_{2m} = (-1)^m h, T_odd = 0
    g_coe[12] = 0.5f * g_coe[0] - g_coe[2] + g_coe[4] - g_coe[6] + g_coe[8] - g_coe[10];
}

// ---------------- fused MLP: h = relu(x@W1+b1)@W2+b2 ; writes h and dis*h ----------------
__global__ __launch_bounds__(256) void mlp_kernel(
    const float* __restrict__ x, const float* __restrict__ W1,
    const float* __restrict__ b1, const float* __restrict__ W2,
    const float* __restrict__ b2, float* __restrict__ h,
    float* __restrict__ hs)
{
    __shared__ __align__(16) float sbuf[64 * 33 + 32 * 64];
    __shared__ __align__(16) float Hs[64 * 65];
    float* Xs = sbuf;
    float* Ws = sbuf + 64 * 33;

    int tid = threadIdx.x;
    int tx = tid & 15;
    int ty = tid >> 4;
    int row0 = blockIdx.x * 64;

    float acc[4][4];
#pragma unroll
    for (int i = 0; i < 4; i++)
#pragma unroll
        for (int j = 0; j < 4; j++) acc[i][j] = 0.f;

    for (int kc = 0; kc < FIN; kc += 32) {
        for (int i = tid; i < 64 * 32; i += 256) {
            int r = i >> 5, k = i & 31;
            int gr = row0 + r;
            Xs[r * 33 + k] = (gr < NN) ? x[gr * FIN + kc + k] : 0.f;
        }
        for (int i = tid; i < 32 * 64; i += 256) {
            int k = i >> 6, j = i & 63;
            Ws[i] = W1[(kc + k) * HID + j];
        }
        __syncthreads();
#pragma unroll
        for (int k = 0; k < 32; k++) {
            float a0 = Xs[(ty * 4 + 0) * 33 + k];
            float a1 = Xs[(ty * 4 + 1) * 33 + k];
            float a2 = Xs[(ty * 4 + 2) * 33 + k];
            float a3 = Xs[(ty * 4 + 3) * 33 + k];
            float4 b = *(const float4*)&Ws[k * 64 + tx * 4];
            acc[0][0] += a0 * b.x; acc[0][1] += a0 * b.y; acc[0][2] += a0 * b.z; acc[0][3] += a0 * b.w;
            acc[1][0] += a1 * b.x; acc[1][1] += a1 * b.y; acc[1][2] += a1 * b.z; acc[1][3] += a1 * b.w;
            acc[2][0] += a2 * b.x; acc[2][1] += a2 * b.y; acc[2][2] += a2 * b.z; acc[2][3] += a2 * b.w;
            acc[3][0] += a3 * b.x; acc[3][1] += a3 * b.y; acc[3][2] += a3 * b.z; acc[3][3] += a3 * b.w;
        }
        __syncthreads();
    }

    float4 bb = *(const float4*)&b1[tx * 4];
#pragma unroll
    for (int i = 0; i < 4; i++) {
        int r = ty * 4 + i;
        Hs[r * 65 + tx * 4 + 0] = fmaxf(acc[i][0] + bb.x, 0.f);
        Hs[r * 65 + tx * 4 + 1] = fmaxf(acc[i][1] + bb.y, 0.f);
        Hs[r * 65 + tx * 4 + 2] = fmaxf(acc[i][2] + bb.z, 0.f);
        Hs[r * 65 + tx * 4 + 3] = fmaxf(acc[i][3] + bb.w, 0.f);
    }
    for (int i = tid; i < 64 * 64; i += 256) sbuf[i] = W2[i];
    __syncthreads();

    float acc2[4][4];
#pragma unroll
    for (int i = 0; i < 4; i++)
#pragma unroll
        for (int j = 0; j < 4; j++) acc2[i][j] = 0.f;

#pragma unroll
    for (int k = 0; k < 64; k++) {
        float a0 = Hs[(ty * 4 + 0) * 65 + k];
        float a1 = Hs[(ty * 4 + 1) * 65 + k];
        float a2 = Hs[(ty * 4 + 2) * 65 + k];
        float a3 = Hs[(ty * 4 + 3) * 65 + k];
        float4 b = *(const float4*)&sbuf[k * 64 + tx * 4];
        acc2[0][0] += a0 * b.x; acc2[0][1] += a0 * b.y; acc2[0][2] += a0 * b.z; acc2[0][3] += a0 * b.w;
        acc2[1][0] += a1 * b.x; acc2[1][1] += a1 * b.y; acc2[1][2] += a1 * b.z; acc2[1][3] += a1 * b.w;
        acc2[2][0] += a2 * b.x; acc2[2][1] += a2 * b.y; acc2[2][2] += a2 * b.z; acc2[2][3] += a2 * b.w;
        acc2[3][0] += a3 * b.x; acc2[3][1] += a3 * b.y; acc2[3][2] += a3 * b.z; acc2[3][3] += a3 * b.w;
    }

    float4 c2 = *(const float4*)&b2[tx * 4];
#pragma unroll
    for (int i = 0; i < 4; i++) {
        int gr = row0 + ty * 4 + i;
        if (gr < NN) {
            float4 o;
            o.x = acc2[i][0] + c2.x;
            o.y = acc2[i][1] + c2.y;
            o.z = acc2[i][2] + c2.z;
            o.w = acc2[i][3] + c2.w;
            *(float4*)&h[gr * HID + tx * 4] = o;
            float dv = g_dis[gr];
            float4 os;
            os.x = dv * o.x; os.y = dv * o.y; os.z = dv * o.z; os.w = dv * o.w;
            *(float4*)&hs[gr * HID + tx * 4] = os;
        }
    }
}

// ---------------- fused Chebyshev propagation (scaled space) ----------------
// Warp per node; two 16-lane halves split edge chunks, each lane owns 4
// features (float4). Gather = pure unweighted sum of scaled rows.
//   first=1: T1s = -dis2*g;              out  = coe[1]*T1s
//   first=0: Tis = -2*dis2*g - T(i-2)s;  out += coe[ci]*Tis
__global__ __launch_bounds__(256) void prop_kernel(
    const float4* __restrict__ v, const float4* __restrict__ prev,
    float4* __restrict__ dst, float4* __restrict__ outv,
    int ci, int first)
{
    int tid = threadIdx.x;
    int node = blockIdx.x * 8 + (tid >> 5);
    if (node >= NN) return;
    int half = (tid >> 4) & 1;
    int lane = tid & 15;
    unsigned hmask = 0xFFFFu << (tid & 16);

    int beg = g_rowptr[node];
    int end = g_rowptr[node + 1];

    float4 acc = make_float4(0.f, 0.f, 0.f, 0.f);
    for (int p = beg + half * 16; p < end; p += 32) {
        int cnt = min(16, end - p);
        int s = (lane < cnt) ? __ldg(&g_esrc[p + lane]) : 0;
        for (int j = 0; j < cnt; j++) {
            int sj = __shfl_sync(hmask, s, j, 16);
            float4 val = __ldg(&v[sj * 16 + lane]);
            acc.x += val.x; acc.y += val.y; acc.z += val.z; acc.w += val.w;
        }
    }
    acc.x += __shfl_xor_sync(0xffffffffu, acc.x, 16);
    acc.y += __shfl_xor_sync(0xffffffffu, acc.y, 16);
    acc.z += __shfl_xor_sync(0xffffffffu, acc.z, 16);
    acc.w += __shfl_xor_sync(0xffffffffu, acc.w, 16);

    int idx = node * 16 + lane;
    float d2 = g_dis2[node];
    float c = g_coe[ci];
    float4 t;
    if (first) {
        t.x = -d2 * acc.x;
        t.y = -d2 * acc.y;
        t.z = -d2 * acc.z;
        t.w = -d2 * acc.w;
    } else {
        float4 pv = __ldg(&prev[idx]);
        float m = -2.f * d2;
        t.x = fmaf(m, acc.x, -pv.x);
        t.y = fmaf(m, acc.y, -pv.y);
        t.z = fmaf(m, acc.z, -pv.z);
        t.w = fmaf(m, acc.w, -pv.w);
    }
    if (half == 0) {
        dst[idx] = t;
    } else {
        float4 o;
        if (first) {
            o.x = c * t.x; o.y = c * t.y; o.z = c * t.z; o.w = c * t.w;
        } else {
            o = outv[idx];
            o.x += c * t.x; o.y += c * t.y; o.z += c * t.z; o.w += c * t.w;
        }
        outv[idx] = o;
    }
}

// ---------------- final: out = coe0/2*h + os/dis  (deg-0: fixup*h) ----------------
__global__ __launch_bounds__(256) void final_kernel(
    float4* __restrict__ outv, const float4* __restrict__ h)
{
    int i = blockIdx.x * 256 + threadIdx.x;
    if (i >= NN * 16) return;
    int node = i >> 4;
    float dis = g_dis[node];
    float4 hv = __ldg(&h[i]);
    float4 o = outv[i];
    if (dis > 0.f) {
        float c0h = 0.5f * g_coe[0];
        float inv = 1.0f / dis;
        o.x = c0h * hv.x + o.x * inv;
        o.y = c0h * hv.y + o.y * inv;
        o.z = c0h * hv.z + o.z * inv;
        o.w = c0h * hv.w + o.w * inv;
    } else {
        float fx = g_coe[12];
        o.x = fx * hv.x; o.y = fx * hv.y; o.z = fx * hv.z; o.w = fx * hv.w;
    }
    outv[i] = o;
}

// ---------------- launch ----------------
extern "C" void kernel_launch(void* const* d_in, const int* in_sizes, int n_in,
                              void* d_out, int out_size) {
    const float* x    = (const float*)d_in[0];
    const void*  ei   = d_in[1];
    const float* W1   = (const float*)d_in[2];
    const float* b1   = (const float*)d_in[3];
    const float* W2   = (const float*)d_in[4];
    const float* b2   = (const float*)d_in[5];
    const float* temp = (const float*)d_in[6];
    float4*      out4 = (float4*)d_out;

    void *pT0, *pT1, *pT2, *pH, *pCntR, *pCntC, *pRowptr, *pCur;
    cudaGetSymbolAddress(&pT0, g_T0);
    cudaGetSymbolAddress(&pT1, g_T1);
    cudaGetSymbolAddress(&pT2, g_T2);
    cudaGetSymbolAddress(&pH,  g_H);
    cudaGetSymbolAddress(&pCntR, g_cnt_row);
    cudaGetSymbolAddress(&pCntC, g_cnt_col);
    cudaGetSymbolAddress(&pRowptr, g_rowptr);
    cudaGetSymbolAddress(&pCur, g_cur);

    // --- graph preprocessing ---
    cudaMemsetAsync(pCntR, 0, NN * sizeof(int), 0);
    cudaMemsetAsync(pCntC, 0, NN * sizeof(int), 0);
    detect_kernel<<<1, 32>>>((const unsigned int*)ei);
    hist_kernel<<<(EE + 255) / 256, 256>>>(ei);
    dis_kernel<<<(NN + 255) / 256, 256>>>();
    int nb = (NN + 1023) / 1024;
    scan1_kernel<<<nb, 1024>>>();
    scan2_kernel<<<1, 1>>>(nb);
    scan3_kernel<<<(NN + 255) / 256, 256>>>();
    cudaMemcpyAsync(pCur, pRowptr, NN * sizeof(int), cudaMemcpyDeviceToDevice, 0);
    scatter_kernel<<<(EE + 255) / 256, 256>>>();

    // --- coefficients ---
    coe_kernel<<<1, 32>>>(temp);

    // --- MLP -> g_H (h) and g_T0 (dis*h = T0 scaled) ---
    mlp_kernel<<<(NN + 63) / 64, 256>>>(x, W1, b1, W2, b2, (float*)pH, (float*)pT0);

    // --- Chebyshev recurrence in scaled space ---
    int pgrid = (NN + 7) / 8;
    prop_kernel<<<pgrid, 256>>>((const float4*)pT0, (const float4*)pT0,
                                (float4*)pT1, out4, 1, 1);
    float4* t0 = (float4*)pT0;
    float4* t1 = (float4*)pT1;
    float4* t2 = (float4*)pT2;
    for (int i = 2; i <= KK; i++) {
        prop_kernel<<<pgrid, 256>>>(t1, t0, t2, out4, i, 0);
        float4* tmp = t0; t0 = t1; t1 = t2; t2 = tmp;
    }

    // --- final unscale + h term ---
    final_kernel<<<(NN * 16 + 255) / 256, 256>>>(out4, (const float4*)pH);
}

// round 9
// speedup vs baseline: 1.1680x; 1.1676x over previous
#include <cuda_runtime.h>
#include <math.h>

#define NN 100000
#define EE 1600000
#define KK 10
#define HID 64
#define FIN 256

// ---------------- scratch ----------------
__device__ __align__(16) float g_T0[NN * HID];
__device__ __align__(16) float g_T1[NN * HID];
__device__ __align__(16) float g_T2[NN * HID];
__device__ __align__(16) float g_H [NN * HID];
__device__ int   g_cnt_row[NN];
__device__ int   g_cnt_col[NN];
__device__ int   g_rowptr[NN + 1];
__device__ int   g_cur[NN];
__device__ float g_dis[NN];    // rsqrt(deg) or 0
__device__ float g_dis2[NN];   // 1/deg or 0  (= dis^2)
__device__ int   g_rows32[EE];
__device__ int   g_cols32[EE];
__device__ int   g_esrc[EE];
__device__ float g_coe[16];
__device__ int   g_tmpinc[NN];
__device__ int   g_bsum[128];
__device__ int   g_boff[128];
__device__ int   g_is64;

// ---------------- dtype detect ----------------
__global__ void detect_kernel(const unsigned int* __restrict__ ei32) {
    if (threadIdx.x != 0 || blockIdx.x != 0) return;
    int zeros = 0;
    for (int i = 0; i < 8; i++)
        if (ei32[2 * i + 1] == 0u) zeros++;
    g_is64 = (zeros == 8) ? 1 : 0;
}

// ---------------- histogram + int->int32 ----------------
__global__ void hist_kernel(const void* __restrict__ eiv) {
    int e = blockIdx.x * blockDim.x + threadIdx.x;
    if (e >= EE) return;
    int r, c;
    if (g_is64) {
        const long long* ei = (const long long*)eiv;
        r = (int)ei[e];
        c = (int)ei[EE + e];
    } else {
        const int* ei = (const int*)eiv;
        r = ei[e];
        c = ei[EE + e];
    }
    if ((unsigned)r >= NN || (unsigned)c >= NN) { r = 0; c = 0; }
    g_rows32[e] = r;
    g_cols32[e] = c;
    atomicAdd(&g_cnt_row[r], 1);
    atomicAdd(&g_cnt_col[c], 1);
}

__global__ void dis_kernel() {
    int i = blockIdx.x * blockDim.x + threadIdx.x;
    if (i >= NN) return;
    int d = g_cnt_row[i];
    g_dis[i]  = (d > 0) ? rsqrtf((float)d) : 0.0f;
    g_dis2[i] = (d > 0) ? (1.0f / (float)d) : 0.0f;
}

// ---------------- scan ----------------
__global__ void scan1_kernel() {
    __shared__ int s[1024];
    int tid = threadIdx.x;
    int i = blockIdx.x * 1024 + tid;
    int v = (i < NN) ? g_cnt_col[i] : 0;
    s[tid] = v;
    __syncthreads();
    for (int off = 1; off < 1024; off <<= 1) {
        int t = 0;
        if (tid >= off) t = s[tid - off];
        __syncthreads();
        s[tid] += t;
        __syncthreads();
    }
    if (i < NN) g_tmpinc[i] = s[tid];
    if (tid == 1023) g_bsum[blockIdx.x] = s[1023];
}

__global__ void scan2_kernel(int nb) {
    if (blockIdx.x == 0 && threadIdx.x == 0) {
        int run = 0;
        for (int b = 0; b < nb; b++) {
            g_boff[b] = run;
            run += g_bsum[b];
        }
    }
}

__global__ void scan3_kernel() {
    int i = blockIdx.x * blockDim.x + threadIdx.x;
    if (i == 0) g_rowptr[0] = 0;
    if (i < NN) g_rowptr[i + 1] = g_tmpinc[i] + g_boff[i >> 10];
}

// ---------------- scatter (src only; weights folded into scaling) ----------------
__global__ void scatter_kernel() {
    int e = blockIdx.x * blockDim.x + threadIdx.x;
    if (e >= EE) return;
    int r = g_rows32[e];
    int c = g_cols32[e];
    int p = atomicAdd(&g_cur[c], 1);
    g_esrc[p] = r;
}

// ---------------- coefficients ----------------
__global__ void coe_kernel(const float* __restrict__ temp) {
    if (blockIdx.x != 0 || threadIdx.x != 0) return;
    double xs[KK + 1];
    float m0[KK + 1], m1[KK + 1], tv[KK + 1];
    for (int j = 0; j <= KK; j++) {
        xs[j] = cos((KK - j + 0.5) * M_PI / (KK + 1));
        tv[j] = temp[j];
    }
    const float f = 2.0f / (KK + 1);
    float s0 = 0.f, s1 = 0.f;
    for (int j = 0; j <= KK; j++) {
        m0[j] = 1.0f;
        m1[j] = (float)xs[j];
        s0 += tv[j] * m0[j];
        s1 += tv[j] * m1[j];
    }
    g_coe[0] = f * s0;
    g_coe[1] = f * s1;
    for (int i = 2; i <= KK; i++) {
        float s = 0.f;
        for (int j = 0; j <= KK; j++) {
            float m2 = (float)(2.0 * xs[j] * (double)m1[j] - (double)m0[j]);
            s += tv[j] * m2;
            m0[j] = m1[j];
            m1[j] = m2;
        }
        g_coe[i] = f * s;
    }
    g_coe[12] = 0.5f * g_coe[0] - g_coe[2] + g_coe[4] - g_coe[6] + g_coe[8] - g_coe[10];
}

// ---------------- fused MLP ----------------
__global__ __launch_bounds__(256) void mlp_kernel(
    const float* __restrict__ x, const float* __restrict__ W1,
    const float* __restrict__ b1, const float* __restrict__ W2,
    const float* __restrict__ b2, float* __restrict__ h,
    float* __restrict__ hs)
{
    __shared__ __align__(16) float sbuf[64 * 33 + 32 * 64];
    __shared__ __align__(16) float Hs[64 * 65];
    float* Xs = sbuf;
    float* Ws = sbuf + 64 * 33;

    int tid = threadIdx.x;
    int tx = tid & 15;
    int ty = tid >> 4;
    int row0 = blockIdx.x * 64;

    float acc[4][4];
#pragma unroll
    for (int i = 0; i < 4; i++)
#pragma unroll
        for (int j = 0; j < 4; j++) acc[i][j] = 0.f;

    for (int kc = 0; kc < FIN; kc += 32) {
        for (int i = tid; i < 64 * 32; i += 256) {
            int r = i >> 5, k = i & 31;
            int gr = row0 + r;
            Xs[r * 33 + k] = (gr < NN) ? x[gr * FIN + kc + k] : 0.f;
        }
        for (int i = tid; i < 32 * 64; i += 256) {
            int k = i >> 6, j = i & 63;
            Ws[i] = W1[(kc + k) * HID + j];
        }
        __syncthreads();
#pragma unroll
        for (int k = 0; k < 32; k++) {
            float a0 = Xs[(ty * 4 + 0) * 33 + k];
            float a1 = Xs[(ty * 4 + 1) * 33 + k];
            float a2 = Xs[(ty * 4 + 2) * 33 + k];
            float a3 = Xs[(ty * 4 + 3) * 33 + k];
            float4 b = *(const float4*)&Ws[k * 64 + tx * 4];
            acc[0][0] += a0 * b.x; acc[0][1] += a0 * b.y; acc[0][2] += a0 * b.z; acc[0][3] += a0 * b.w;
            acc[1][0] += a1 * b.x; acc[1][1] += a1 * b.y; acc[1][2] += a1 * b.z; acc[1][3] += a1 * b.w;
            acc[2][0] += a2 * b.x; acc[2][1] += a2 * b.y; acc[2][2] += a2 * b.z; acc[2][3] += a2 * b.w;
            acc[3][0] += a3 * b.x; acc[3][1] += a3 * b.y; acc[3][2] += a3 * b.z; acc[3][3] += a3 * b.w;
        }
        __syncthreads();
    }

    float4 bb = *(const float4*)&b1[tx * 4];
#pragma unroll
    for (int i = 0; i < 4; i++) {
        int r = ty * 4 + i;
        Hs[r * 65 + tx * 4 + 0] = fmaxf(acc[i][0] + bb.x, 0.f);
        Hs[r * 65 + tx * 4 + 1] = fmaxf(acc[i][1] + bb.y, 0.f);
        Hs[r * 65 + tx * 4 + 2] = fmaxf(acc[i][2] + bb.z, 0.f);
        Hs[r * 65 + tx * 4 + 3] = fmaxf(acc[i][3] + bb.w, 0.f);
    }
    for (int i = tid; i < 64 * 64; i += 256) sbuf[i] = W2[i];
    __syncthreads();

    float acc2[4][4];
#pragma unroll
    for (int i = 0; i < 4; i++)
#pragma unroll
        for (int j = 0; j < 4; j++) acc2[i][j] = 0.f;

#pragma unroll
    for (int k = 0; k < 64; k++) {
        float a0 = Hs[(ty * 4 + 0) * 65 + k];
        float a1 = Hs[(ty * 4 + 1) * 65 + k];
        float a2 = Hs[(ty * 4 + 2) * 65 + k];
        float a3 = Hs[(ty * 4 + 3) * 65 + k];
        float4 b = *(const float4*)&sbuf[k * 64 + tx * 4];
        acc2[0][0] += a0 * b.x; acc2[0][1] += a0 * b.y; acc2[0][2] += a0 * b.z; acc2[0][3] += a0 * b.w;
        acc2[1][0] += a1 * b.x; acc2[1][1] += a1 * b.y; acc2[1][2] += a1 * b.z; acc2[1][3] += a1 * b.w;
        acc2[2][0] += a2 * b.x; acc2[2][1] += a2 * b.y; acc2[2][2] += a2 * b.z; acc2[2][3] += a2 * b.w;
        acc2[3][0] += a3 * b.x; acc2[3][1] += a3 * b.y; acc2[3][2] += a3 * b.z; acc2[3][3] += a3 * b.w;
    }

    float4 c2 = *(const float4*)&b2[tx * 4];
#pragma unroll
    for (int i = 0; i < 4; i++) {
        int gr = row0 + ty * 4 + i;
        if (gr < NN) {
            float4 o;
            o.x = acc2[i][0] + c2.x;
            o.y = acc2[i][1] + c2.y;
            o.z = acc2[i][2] + c2.z;
            o.w = acc2[i][3] + c2.w;
            *(float4*)&h[gr * HID + tx * 4] = o;
            float dv = g_dis[gr];
            float4 os;
            os.x = dv * o.x; os.y = dv * o.y; os.z = dv * o.z; os.w = dv * o.w;
            *(float4*)&hs[gr * HID + tx * 4] = os;
        }
    }
}

// ---------------- fused Chebyshev propagation (scaled space, uniform index load) ----------------
// Warp per node, each lane owns 2 features (float2). Edge indices read uniformly
// (all lanes same address; sequential per warp -> L1-resident). No shuffles.
//   first: T1s = -dis2*g;               out  = coe[1]*T1s
//   mid:   Tis = -2*dis2*g - T(i-2)s;   out += coe[ci]*Tis
//   last:  additionally out = coe0/2*h + out/dis  (deg-0: fixup*h), dst not written
__global__ __launch_bounds__(256) void prop_kernel(
    const float2* __restrict__ v, const float2* __restrict__ prev,
    float2* __restrict__ dst, float2* __restrict__ outv,
    const float2* __restrict__ hfeat,
    int ci, int first, int last)
{
    int tid = threadIdx.x;
    int node = blockIdx.x * 8 + (tid >> 5);
    if (node >= NN) return;
    int lane = tid & 31;

    int beg = __ldg(&g_rowptr[node]);
    int end = __ldg(&g_rowptr[node + 1]);

    float2 a0 = make_float2(0.f, 0.f);
    float2 a1 = make_float2(0.f, 0.f);
    float2 a2 = make_float2(0.f, 0.f);
    float2 a3 = make_float2(0.f, 0.f);

    int p = beg;
    for (; p + 4 <= end; p += 4) {
        int s0 = __ldg(&g_esrc[p + 0]);
        int s1 = __ldg(&g_esrc[p + 1]);
        int s2 = __ldg(&g_esrc[p + 2]);
        int s3 = __ldg(&g_esrc[p + 3]);
        float2 v0 = __ldg(&v[s0 * 32 + lane]);
        float2 v1 = __ldg(&v[s1 * 32 + lane]);
        float2 v2 = __ldg(&v[s2 * 32 + lane]);
        float2 v3 = __ldg(&v[s3 * 32 + lane]);
        a0.x += v0.x; a0.y += v0.y;
        a1.x += v1.x; a1.y += v1.y;
        a2.x += v2.x; a2.y += v2.y;
        a3.x += v3.x; a3.y += v3.y;
    }
    for (; p < end; p++) {
        int s0 = __ldg(&g_esrc[p]);
        float2 v0 = __ldg(&v[s0 * 32 + lane]);
        a0.x += v0.x; a0.y += v0.y;
    }
    float2 acc;
    acc.x = (a0.x + a1.x) + (a2.x + a3.x);
    acc.y = (a0.y + a1.y) + (a2.y + a3.y);

    int idx = node * 32 + lane;
    float d2 = __ldg(&g_dis2[node]);
    float c = g_coe[ci];
    float2 t;
    if (first) {
        t.x = -d2 * acc.x;
        t.y = -d2 * acc.y;
    } else {
        float2 pv = __ldg(&prev[idx]);
        float m = -2.f * d2;
        t.x = fmaf(m, acc.x, -pv.x);
        t.y = fmaf(m, acc.y, -pv.y);
    }
    if (!last) {
        dst[idx] = t;
        float2 o;
        if (first) {
            o.x = c * t.x; o.y = c * t.y;
        } else {
            o = outv[idx];
            o.x += c * t.x; o.y += c * t.y;
        }
        outv[idx] = o;
    } else {
        // fuse final unscale: out = coe0/2*h + (oacc + c*t)/dis ; deg-0: fixup*h
        float2 o = outv[idx];
        o.x += c * t.x;
        o.y += c * t.y;
        float2 hv = __ldg(&hfeat[idx]);
        float dis = __ldg(&g_dis[node]);
        float2 r;
        if (dis > 0.f) {
            float c0h = 0.5f * g_coe[0];
            float inv = 1.0f / dis;
            r.x = fmaf(c0h, hv.x, o.x * inv);
            r.y = fmaf(c0h, hv.y, o.y * inv);
        } else {
            float fx = g_coe[12];
            r.x = fx * hv.x;
            r.y = fx * hv.y;
        }
        outv[idx] = r;
    }
}

// ---------------- launch ----------------
extern "C" void kernel_launch(void* const* d_in, const int* in_sizes, int n_in,
                              void* d_out, int out_size) {
    const float* x    = (const float*)d_in[0];
    const void*  ei   = d_in[1];
    const float* W1   = (const float*)d_in[2];
    const float* b1   = (const float*)d_in[3];
    const float* W2   = (const float*)d_in[4];
    const float* b2   = (const float*)d_in[5];
    const float* temp = (const float*)d_in[6];
    float2*      out2 = (float2*)d_out;

    void *pT0, *pT1, *pT2, *pH, *pCntR, *pCntC, *pRowptr, *pCur;
    cudaGetSymbolAddress(&pT0, g_T0);
    cudaGetSymbolAddress(&pT1, g_T1);
    cudaGetSymbolAddress(&pT2, g_T2);
    cudaGetSymbolAddress(&pH,  g_H);
    cudaGetSymbolAddress(&pCntR, g_cnt_row);
    cudaGetSymbolAddress(&pCntC, g_cnt_col);
    cudaGetSymbolAddress(&pRowptr, g_rowptr);
    cudaGetSymbolAddress(&pCur, g_cur);

    // --- graph preprocessing ---
    cudaMemsetAsync(pCntR, 0, NN * sizeof(int), 0);
    cudaMemsetAsync(pCntC, 0, NN * sizeof(int), 0);
    detect_kernel<<<1, 32>>>((const unsigned int*)ei);
    hist_kernel<<<(EE + 255) / 256, 256>>>(ei);
    dis_kernel<<<(NN + 255) / 256, 256>>>();
    int nb = (NN + 1023) / 1024;
    scan1_kernel<<<nb, 1024>>>();
    scan2_kernel<<<1, 1>>>(nb);
    scan3_kernel<<<(NN + 255) / 256, 256>>>();
    cudaMemcpyAsync(pCur, pRowptr, NN * sizeof(int), cudaMemcpyDeviceToDevice, 0);
    scatter_kernel<<<(EE + 255) / 256, 256>>>();

    // --- coefficients ---
    coe_kernel<<<1, 32>>>(temp);

    // --- MLP -> g_H (h) and g_T0 (dis*h) ---
    mlp_kernel<<<(NN + 63) / 64, 256>>>(x, W1, b1, W2, b2, (float*)pH, (float*)pT0);

    // --- Chebyshev recurrence in scaled space, final fused into last prop ---
    int pgrid = (NN + 7) / 8;
    prop_kernel<<<pgrid, 256>>>((const float2*)pT0, (const float2*)pT0,
                                (float2*)pT1, out2, (const float2*)pH, 1, 1, 0);
    float2* t0 = (float2*)pT0;
    float2* t1 = (float2*)pT1;
    float2* t2 = (float2*)pT2;
    for (int i = 2; i <= KK; i++) {
        int last = (i == KK) ? 1 : 0;
        prop_kernel<<<pgrid, 256>>>(t1, t0, t2, out2, (const float2*)pH, i, 0, last);
        float2* tmp = t0; t0 = t1; t1 = t2; t2 = tmp;
    }
}